// round 15
// baseline (speedup 1.0000x reference)
#include <cuda_runtime.h>
#include <cuda_fp16.h>
#include <math.h>
#include <stdint.h>

// Problem constants
#define BATCH 8
#define HH 64
#define WW 64
#define DD 512
#define NHEAD 16
#define DK 32
#define WS 8
#define SHIFT 4
#define TOK (BATCH*HH*WW)      // 32768
#define LAYERS 4
#define SCALE 0.17677669529663687f  // 1/sqrt(32)

// -------------------- scratch (allocation-free: __device__ globals) ------------
__device__ __align__(128) __half g_xn  [ (size_t)TOK * DD ];        // 32 MB
__device__ __align__(128) __half g_hb  [ (size_t)TOK * DD ];        // 32 MB
__device__ __align__(128) __half g_ao  [ (size_t)TOK * DD ];        // 32 MB
__device__ __align__(128) __half g_hid [ (size_t)TOK * 4 * DD ];    // 128 MB
__device__ __align__(128) __half g_wf  [ 12582912 ];                // 24 MB, fp16 [N][K]
__device__ __align__(128) __half g_qkvh[ (size_t)TOK * 3 * DD ];    // 96 MB fp16 q|k|v
__device__ float g_bqkv[ LAYERS * 3 * DD ];

// ==================== helpers ==================================================
__device__ __forceinline__ uint32_t smem_u32(const void* p) {
    uint32_t a;
    asm("{ .reg .u64 t; cvta.to.shared.u64 t, %1; cvt.u32.u64 %0, t; }" : "=r"(a) : "l"(p));
    return a;
}
#define CP_ASYNC16(dst, src) \
    asm volatile("cp.async.cg.shared.global [%0], [%1], 16;" :: "r"(dst), "l"(src))
#define CP_COMMIT() asm volatile("cp.async.commit_group;" ::: "memory")
#define CP_WAIT1()  asm volatile("cp.async.wait_group 1;" ::: "memory")
#define CP_WAIT0()  asm volatile("cp.async.wait_group 0;" ::: "memory")

__device__ __forceinline__ void ldmx4(uint32_t& r0, uint32_t& r1, uint32_t& r2, uint32_t& r3,
                                      uint32_t addr) {
    asm volatile("ldmatrix.sync.aligned.m8n8.x4.shared.b16 {%0,%1,%2,%3}, [%4];"
                 : "=r"(r0), "=r"(r1), "=r"(r2), "=r"(r3) : "r"(addr));
}
__device__ __forceinline__ void ldmx4t(uint32_t& r0, uint32_t& r1, uint32_t& r2, uint32_t& r3,
                                       uint32_t addr) {
    asm volatile("ldmatrix.sync.aligned.m8n8.x4.trans.shared.b16 {%0,%1,%2,%3}, [%4];"
                 : "=r"(r0), "=r"(r1), "=r"(r2), "=r"(r3) : "r"(addr));
}
__device__ __forceinline__ void mma16816(float* d, uint32_t a0, uint32_t a1, uint32_t a2,
                                         uint32_t a3, uint32_t b0, uint32_t b1) {
    asm volatile("mma.sync.aligned.m16n8k16.row.col.f32.f16.f16.f32 "
                 "{%0,%1,%2,%3},{%4,%5,%6,%7},{%8,%9},{%0,%1,%2,%3};"
                 : "+f"(d[0]), "+f"(d[1]), "+f"(d[2]), "+f"(d[3])
                 : "r"(a0), "r"(a1), "r"(a2), "r"(a3), "r"(b0), "r"(b1));
}

__device__ __forceinline__ float gelu_tanh(float x) {
    float x3 = x * x * x;
    return 0.5f * x * (1.0f + tanhf(0.7978845608028654f * (x + 0.044715f * x3)));
}
__device__ __forceinline__ uint32_t packh2(float a, float b) {
    __half2 h = __floats2half2_rn(a, b);
    return *(uint32_t*)&h;
}

// ==================== fused QKV weight convert + bias concat ===================
__global__ void convqkv_kernel(const float* __restrict__ Wq, const float* __restrict__ Wkv,
                               const float* __restrict__ bq, const float* __restrict__ bkv,
                               __half* __restrict__ dst, float* __restrict__ bias) {
    int l = blockIdx.z;
    if (blockIdx.y == 16) {
        if (blockIdx.x != 0) return;
        int t = threadIdx.y * 32 + threadIdx.x;
        for (int i = t; i < 1536; i += 256)
            bias[l * 1536 + i] = (i < 512) ? bq[l * 512 + i] : bkv[l * 1024 + (i - 512)];
        return;
    }
    __shared__ float tt[32][33];
    int n0 = blockIdx.x * 32, k0 = blockIdx.y * 32;
    const float* src;
    int N, nc0;
    if (n0 < 512) { src = Wq + (size_t)l * 512 * 512; N = 512; nc0 = n0; }
    else          { src = Wkv + (size_t)l * 512 * 1024; N = 1024; nc0 = n0 - 512; }
    dst += (size_t)l * 1536 * 512;
    int tx = threadIdx.x, ty = threadIdx.y;
#pragma unroll
    for (int i = 0; i < 4; i++)
        tt[ty + i * 8][tx] = src[(size_t)(k0 + ty + i * 8) * N + nc0 + tx];
    __syncthreads();
#pragma unroll
    for (int i = 0; i < 4; i++)
        dst[(size_t)(n0 + ty + i * 8) * 512 + k0 + tx] = __float2half_rn(tt[tx][ty + i * 8]);
}

// ==================== weight convert: W[K,N] -> Wf[N,K] fp16 ===================
__global__ void convw_kernel(const float* __restrict__ src, __half* __restrict__ dst,
                             int K, int N, size_t zstride) {
    __shared__ float t[32][33];
    int n0 = blockIdx.x * 32, k0 = blockIdx.y * 32;
    src += (size_t)blockIdx.z * K * N;
    dst += (size_t)blockIdx.z * zstride;
    int tx = threadIdx.x, ty = threadIdx.y;
#pragma unroll
    for (int i = 0; i < 4; i++)
        t[ty + i * 8][tx] = src[(size_t)(k0 + ty + i * 8) * N + n0 + tx];
    __syncthreads();
#pragma unroll
    for (int i = 0; i < 4; i++) {
        int n = n0 + ty + i * 8;
        int k = k0 + tx;
        dst[(size_t)n * K + k] = __float2half_rn(t[tx][ty + i * 8]);
    }
}

// ==================== LayerNorm -> fp16 ========================================
__global__ __launch_bounds__(128) void ln_kernel(const float* __restrict__ x,
                                                 const float* __restrict__ gamma,
                                                 const float* __restrict__ beta,
                                                 __half* __restrict__ out) {
    int tok = blockIdx.x;
    int tid = threadIdx.x;
    const float* xr = x + (size_t)tok * DD;
    float v[4];
#pragma unroll
    for (int i = 0; i < 4; i++) v[i] = xr[tid + i * 128];

    __shared__ float s1[4], s2[4];
    int lane = tid & 31, warp = tid >> 5;

    float s = v[0] + v[1] + v[2] + v[3];
#pragma unroll
    for (int o = 16; o > 0; o >>= 1) s += __shfl_xor_sync(0xffffffffu, s, o);
    if (lane == 0) s1[warp] = s;
    __syncthreads();
    float mean = (s1[0] + s1[1] + s1[2] + s1[3]) * (1.0f / DD);

    float sq = 0.f;
#pragma unroll
    for (int i = 0; i < 4; i++) { float d = v[i] - mean; sq += d * d; }
#pragma unroll
    for (int o = 16; o > 0; o >>= 1) sq += __shfl_xor_sync(0xffffffffu, sq, o);
    if (lane == 0) s2[warp] = sq;
    __syncthreads();
    float var = (s2[0] + s2[1] + s2[2] + s2[3]) * (1.0f / DD);
    float rs = rsqrtf(var + 1e-5f);

    __half* orow = out + (size_t)tok * DD;
#pragma unroll
    for (int i = 0; i < 4; i++) {
        int c = tid + i * 128;
        orow[c] = __float2half_rn((v[i] - mean) * rs * gamma[c] + beta[c]);
    }
}

// ==================== fp16 mma GEMM, 256x128 tile ==============================
// C[M,N] = epilogue(A[M,K] @ Wf[N,K]^T)
// 8 warps: 4 m-strips x 2 n-strips, each warp 64x64
// mode 0: fp32 out (+bias, +optional resid)
// mode 1: gelu -> fp16 out      mode 2: bias only -> fp16 out
#define GSTAGES 3
#define GSTAGE_BYTES 49152     // A 32KB + B 16KB
#define GSB_OFF 32768
#define GEMM_SMEM (GSTAGES * GSTAGE_BYTES)

__global__ __launch_bounds__(256, 1) void gemm_mma(const __half* __restrict__ A,
                                                   const __half* __restrict__ Wf,
                                                   const float* __restrict__ bias,
                                                   const float* __restrict__ resid,
                                                   void* __restrict__ Cout,
                                                   int N, int K, int mode) {
    extern __shared__ char smem[];
    uint32_t sb = smem_u32(smem);
    int tid = threadIdx.x, wid = tid >> 5, lane = tid & 31;
    int bm0 = blockIdx.y * 256, bn0 = blockIdx.x * 128;
    int wm = (wid & 3) * 64, wn = (wid >> 2) * 64;

    float acc[4][8][4];
#pragma unroll
    for (int t = 0; t < 4; t++)
#pragma unroll
        for (int n = 0; n < 8; n++)
#pragma unroll
            for (int r = 0; r < 4; r++) acc[t][n][r] = 0.f;

    const int nch = K >> 6;

    // loader: pairs of threads cover one 128B row; A has 256 rows (two 128-row groups)
    int lr = tid >> 1;
    int lc0 = (tid & 1) * 4;
    const __half* agp0 = A + (size_t)(bm0 + lr) * K + lc0 * 8;
    const __half* agp1 = A + (size_t)(bm0 + 128 + lr) * K + lc0 * 8;
    const __half* bgp  = Wf + (size_t)(bn0 + lr) * K + lc0 * 8;
    uint32_t sw[4];
#pragma unroll
    for (int it = 0; it < 4; it++)
        sw[it] = (uint32_t)lr * 128 + (uint32_t)(((lc0 + it) ^ (lr & 7)) << 4);

    // ldmatrix per-warp bases
    int arow[4], arx[4];
#pragma unroll
    for (int t = 0; t < 4; t++) {
        int r = wm + t * 16 + (lane & 15);
        arow[t] = r * 128;
        arx[t] = r & 7;
    }
    int ach = lane >> 4;
    int brow[4], brx[4];
#pragma unroll
    for (int p = 0; p < 4; p++) {
        int n = wn + p * 16 + (lane & 7) + ((lane >> 4) << 3);
        brow[p] = n * 128;
        brx[p] = n & 7;
    }
    int bch = (lane >> 3) & 1;

    auto issue_stage = [&](int c, int stage) {
        uint32_t st = sb + (uint32_t)stage * GSTAGE_BYTES;
        const __half* a0 = agp0 + (size_t)c * 64;
        const __half* a1 = agp1 + (size_t)c * 64;
        const __half* bg = bgp + (size_t)c * 64;
#pragma unroll
        for (int it = 0; it < 4; it++) CP_ASYNC16(st + sw[it], a0 + it * 8);
#pragma unroll
        for (int it = 0; it < 4; it++) CP_ASYNC16(st + 16384 + sw[it], a1 + it * 8);
#pragma unroll
        for (int it = 0; it < 4; it++) CP_ASYNC16(st + GSB_OFF + sw[it], bg + it * 8);
        CP_COMMIT();
    };

    issue_stage(0, 0);
    issue_stage(1, 1);

    int buf = 0, nbuf = 2;
    for (int c = 0; c < nch; c++) {
        if (c == nch - 1) { CP_WAIT0(); } else { CP_WAIT1(); }
        __syncthreads();
        if (c + 2 < nch) issue_stage(c + 2, nbuf);

        uint32_t stA = sb + (uint32_t)buf * GSTAGE_BYTES;
        uint32_t stB = stA + GSB_OFF;
#pragma unroll
        for (int ks = 0; ks < 4; ks++) {
            uint32_t a[4][4];
#pragma unroll
            for (int t = 0; t < 4; t++) {
                uint32_t ad = stA + arow[t] + (uint32_t)((((ks << 1) + ach) ^ arx[t]) << 4);
                ldmx4(a[t][0], a[t][1], a[t][2], a[t][3], ad);
            }
#pragma unroll
            for (int p = 0; p < 4; p++) {
                uint32_t b0, b1, b2, b3;
                uint32_t bd = stB + brow[p] + (uint32_t)((((ks << 1) + bch) ^ brx[p]) << 4);
                ldmx4(b0, b1, b2, b3, bd);
#pragma unroll
                for (int t = 0; t < 4; t++) {
                    mma16816(acc[t][2 * p],     a[t][0], a[t][1], a[t][2], a[t][3], b0, b1);
                    mma16816(acc[t][2 * p + 1], a[t][0], a[t][1], a[t][2], a[t][3], b2, b3);
                }
            }
        }
        buf = (buf + 1 == GSTAGES) ? 0 : buf + 1;
        nbuf = (nbuf + 1 == GSTAGES) ? 0 : nbuf + 1;
        __syncthreads();
    }

    // epilogue
    int cbase = bn0 + wn;
#pragma unroll
    for (int t = 0; t < 4; t++) {
        int r0 = bm0 + wm + t * 16 + (lane >> 2);
#pragma unroll
        for (int half = 0; half < 2; half++) {
            int r = r0 + half * 8;
            if (mode == 0) {
                float* crow = (float*)Cout + (size_t)r * N + cbase;
                const float* rrow = resid ? resid + (size_t)r * N + cbase : (const float*)0;
#pragma unroll
                for (int p = 0; p < 8; p++) {
                    int c = p * 8 + (lane & 3) * 2;
                    float v0 = acc[t][p][half * 2 + 0] + bias[cbase + c];
                    float v1 = acc[t][p][half * 2 + 1] + bias[cbase + c + 1];
                    if (rrow) { v0 += rrow[c]; v1 += rrow[c + 1]; }
                    float2 o; o.x = v0; o.y = v1;
                    *(float2*)(crow + c) = o;
                }
            } else {
                __half* orow = (__half*)Cout + (size_t)r * N;
                int do_g = (mode == 1);
#pragma unroll
                for (int p = 0; p < 8; p++) {
                    int c = p * 8 + (lane & 3) * 2;
                    float v0 = acc[t][p][half * 2 + 0] + bias[cbase + c];
                    float v1 = acc[t][p][half * 2 + 1] + bias[cbase + c + 1];
                    if (do_g) { v0 = gelu_tanh(v0); v1 = gelu_tanh(v1); }
                    int cn = cbase + c;
                    *(uint32_t*)(orow + cn) = packh2(v0, v1);
                }
            }
        }
    }
}

// ==================== Tensor-core shifted-window attention =====================
__device__ __forceinline__ int region_id(int hs, int ws) {
    int rh = (hs < HH - WS) ? 0 : (hs < HH - SHIFT) ? 1 : 2;
    int rw = (ws < WW - WS) ? 0 : (ws < WW - SHIFT) ? 1 : 2;
    return rh * 3 + rw;
}

// one block per (batch, window, head); 4 warps x 16 queries
__global__ __launch_bounds__(128) void attn_kernel(const __half* __restrict__ qkv,
                                                   const float* __restrict__ table,
                                                   __half* __restrict__ out) {
    __shared__ __align__(16) __half Qs[64][40];
    __shared__ __align__(16) __half Ks[64][40];
    __shared__ __align__(16) __half Vs[64][40];
    __shared__ float T[225];
    __shared__ char RG[64];

    int bi = blockIdx.x;
    int nh  = bi & 15; bi >>= 4;
    int nww = bi & 7;  bi >>= 3;
    int nwh = bi & 7;  bi >>= 3;
    int b = bi;
    int tid = threadIdx.x;
    int lane = tid & 31, wid = tid >> 5;

    for (int i = tid; i < 225; i += 128) T[i] = table[i * NHEAD + nh];
    if (tid < 64)
        RG[tid] = (char)region_id(nwh * WS + (tid >> 3), nww * WS + (tid & 7));

    for (int idx = tid; idx < 256; idx += 128) {
        int e = idx >> 2, c = idx & 3;
        int h = (nwh * WS + (e >> 3) + SHIFT) & (HH - 1);
        int w = (nww * WS + (e & 7) + SHIFT) & (WW - 1);
        size_t tok = ((size_t)b * HH + h) * WW + w;
        const __half* base = qkv + tok * (3 * DD) + nh * DK + c * 8;
        *(uint4*)&Qs[e][c * 8] = *(const uint4*)(base);
        *(uint4*)&Ks[e][c * 8] = *(const uint4*)(base + DD);
        *(uint4*)&Vs[e][c * 8] = *(const uint4*)(base + 2 * DD);
    }
    __syncthreads();

    int qbase = wid * 16;
    int lrow = (lane & 7) + ((lane >> 3) & 1) * 8;
    int lcol = (lane >> 4) * 8;

    uint32_t aq[2][4];
#pragma unroll
    for (int k2 = 0; k2 < 2; k2++) {
        uint32_t ad = smem_u32(&Qs[qbase + lrow][k2 * 16 + lcol]);
        ldmx4(aq[k2][0], aq[k2][1], aq[k2][2], aq[k2][3], ad);
    }

    float sacc[8][4];
#pragma unroll
    for (int j = 0; j < 8; j++) {
        sacc[j][0] = sacc[j][1] = sacc[j][2] = sacc[j][3] = 0.f;
        uint32_t bk[4];
        uint32_t bd = smem_u32(&Ks[8 * j + (lane & 7)][(lane >> 3) * 8]);
        ldmx4(bk[0], bk[1], bk[2], bk[3], bd);
        mma16816(sacc[j], aq[0][0], aq[0][1], aq[0][2], aq[0][3], bk[0], bk[1]);
        mma16816(sacc[j], aq[1][0], aq[1][1], aq[1][2], aq[1][3], bk[2], bk[3]);
    }

    int g = lane >> 2, qp = lane & 3;
    int q0 = qbase + g, q1 = q0 + 8;
    int iq0 = q0 >> 3, jq = q0 & 7;
    int iq1 = q1 >> 3;
    char rg0 = RG[q0], rg1 = RG[q1];
    float m0 = -1e30f, m1 = -1e30f;
#pragma unroll
    for (int j = 0; j < 8; j++) {
#pragma unroll
        for (int c = 0; c < 4; c++) {
            int e = 8 * j + 2 * qp + (c & 1);
            int ik = e >> 3, jk = e & 7;
            int iqr = (c < 2) ? iq0 : iq1;
            char rgr = (c < 2) ? rg0 : rg1;
            float s = sacc[j][c] * SCALE + T[(iqr - ik + 7) * 15 + (jq - jk + 7)];
            if (RG[e] != rgr) s = -1e9f;
            sacc[j][c] = s;
            if (c < 2) m0 = fmaxf(m0, s); else m1 = fmaxf(m1, s);
        }
    }
    m0 = fmaxf(m0, __shfl_xor_sync(0xffffffffu, m0, 1));
    m0 = fmaxf(m0, __shfl_xor_sync(0xffffffffu, m0, 2));
    m1 = fmaxf(m1, __shfl_xor_sync(0xffffffffu, m1, 1));
    m1 = fmaxf(m1, __shfl_xor_sync(0xffffffffu, m1, 2));

    float d0 = 0.f, d1 = 0.f;
#pragma unroll
    for (int j = 0; j < 8; j++) {
#pragma unroll
        for (int c = 0; c < 4; c++) {
            float p = expf(sacc[j][c] - ((c < 2) ? m0 : m1));
            sacc[j][c] = p;
            if (c < 2) d0 += p; else d1 += p;
        }
    }
    d0 += __shfl_xor_sync(0xffffffffu, d0, 1);
    d0 += __shfl_xor_sync(0xffffffffu, d0, 2);
    d1 += __shfl_xor_sync(0xffffffffu, d1, 1);
    d1 += __shfl_xor_sync(0xffffffffu, d1, 2);
    float inv0 = 1.0f / d0, inv1 = 1.0f / d1;

    uint32_t ap[4][4];
#pragma unroll
    for (int t = 0; t < 4; t++) {
        ap[t][0] = packh2(sacc[2 * t][0],     sacc[2 * t][1]);
        ap[t][1] = packh2(sacc[2 * t][2],     sacc[2 * t][3]);
        ap[t][2] = packh2(sacc[2 * t + 1][0], sacc[2 * t + 1][1]);
        ap[t][3] = packh2(sacc[2 * t + 1][2], sacc[2 * t + 1][3]);
    }

    float oacc[4][4];
#pragma unroll
    for (int m = 0; m < 4; m++)
        oacc[m][0] = oacc[m][1] = oacc[m][2] = oacc[m][3] = 0.f;
#pragma unroll
    for (int u = 0; u < 4; u++) {
        uint32_t bv[8];
        uint32_t vd0 = smem_u32(&Vs[16 * u + lrow][lcol]);
        ldmx4t(bv[0], bv[1], bv[2], bv[3], vd0);
        uint32_t vd1 = smem_u32(&Vs[16 * u + lrow][16 + lcol]);
        ldmx4t(bv[4], bv[5], bv[6], bv[7], vd1);
#pragma unroll
        for (int m = 0; m < 4; m++)
            mma16816(oacc[m], ap[u][0], ap[u][1], ap[u][2], ap[u][3],
                     bv[2 * m], bv[2 * m + 1]);
    }

    int h0 = (nwh * WS + iq0 + SHIFT) & (HH - 1);
    int h1 = (nwh * WS + iq1 + SHIFT) & (HH - 1);
    int w0 = (nww * WS + jq + SHIFT) & (WW - 1);
    size_t t0 = ((size_t)b * HH + h0) * WW + w0;
    size_t t1 = ((size_t)b * HH + h1) * WW + w0;
    __half* o0 = out + t0 * DD + nh * DK + 2 * qp;
    __half* o1 = out + t1 * DD + nh * DK + 2 * qp;
#pragma unroll
    for (int m = 0; m < 4; m++) {
        *(uint32_t*)(o0 + 8 * m) = packh2(oacc[m][0] * inv0, oacc[m][1] * inv0);
        *(uint32_t*)(o1 + 8 * m) = packh2(oacc[m][2] * inv1, oacc[m][3] * inv1);
    }
}

// ==================== driver ===================================================
extern "C" void kernel_launch(void* const* d_in, const int* in_sizes, int n_in,
                              void* d_out, int out_size) {
    const float* x_in      = (const float*)d_in[0];
    const float* Wq        = (const float*)d_in[3];
    const float* bq        = (const float*)d_in[4];
    const float* Wkv       = (const float*)d_in[5];
    const float* bkv       = (const float*)d_in[6];
    const float* Wo        = (const float*)d_in[7];
    const float* bo        = (const float*)d_in[8];
    const float* rel_table = (const float*)d_in[9];
    const float* ln1_g     = (const float*)d_in[10];
    const float* ln1_b     = (const float*)d_in[11];
    const float* ln2_g     = (const float*)d_in[12];
    const float* ln2_b     = (const float*)d_in[13];
    const float* W1        = (const float*)d_in[14];
    const float* b1        = (const float*)d_in[15];
    const float* W2        = (const float*)d_in[16];
    const float* b2        = (const float*)d_in[17];

    float* x = (float*)d_out;

    __half *xn, *hb, *ao, *hid, *wf, *qkv;
    float *bqkv;
    cudaGetSymbolAddress((void**)&xn,   g_xn);
    cudaGetSymbolAddress((void**)&hb,   g_hb);
    cudaGetSymbolAddress((void**)&ao,   g_ao);
    cudaGetSymbolAddress((void**)&hid,  g_hid);
    cudaGetSymbolAddress((void**)&wf,   g_wf);
    cudaGetSymbolAddress((void**)&qkv,  g_qkvh);
    cudaGetSymbolAddress((void**)&bqkv, g_bqkv);

    cudaFuncSetAttribute(gemm_mma, cudaFuncAttributeMaxDynamicSharedMemorySize, GEMM_SMEM);

    const size_t off_qkv = 0;                                   // [1536][512] per layer
    const size_t off_o   = off_qkv + (size_t)LAYERS * 1536 * 512;
    const size_t off_1   = off_o   + (size_t)LAYERS * 512 * 512;
    const size_t off_2   = off_1   + (size_t)LAYERS * 2048 * 512;

    dim3 tb(32, 8);
    convqkv_kernel<<<dim3(48, 17, LAYERS), tb>>>(Wq, Wkv, bq, bkv, wf + off_qkv, bqkv);
    convw_kernel<<<dim3(512 / 32,  512 / 32,  LAYERS), tb>>>(Wo, wf + off_o, 512, 512,
                                                             (size_t)512 * 512);
    convw_kernel<<<dim3(2048 / 32, 512 / 32,  LAYERS), tb>>>(W1, wf + off_1, 512, 2048,
                                                             (size_t)2048 * 512);
    convw_kernel<<<dim3(512 / 32,  2048 / 32, LAYERS), tb>>>(W2, wf + off_2, 2048, 512,
                                                             (size_t)512 * 2048);

    cudaMemcpyAsync(x, x_in, (size_t)TOK * DD * sizeof(float),
                    cudaMemcpyDeviceToDevice, 0);

    for (int l = 0; l < LAYERS; l++) {
        const __half* wqkv_l = wf + off_qkv + (size_t)l * 1536 * 512;
        const __half* wo_l   = wf + off_o   + (size_t)l * 512 * 512;
        const __half* w1_l   = wf + off_1   + (size_t)l * 2048 * 512;
        const __half* w2_l   = wf + off_2   + (size_t)l * 512 * 2048;
        const float* bqkv_l = bqkv + (size_t)l * 3 * DD;
        const float* bo_l   = bo   + (size_t)l * DD;
        const float* tbl_l  = rel_table + (size_t)l * 225 * NHEAD;
        const float* b1_l   = b1   + (size_t)l * 4 * DD;
        const float* b2_l   = b2   + (size_t)l * DD;

        ln_kernel<<<TOK, 128>>>(x, ln1_g + l * DD, ln1_b + l * DD, xn);
        gemm_mma<<<dim3(1536 / 128, TOK / 256), 256, GEMM_SMEM>>>(
            xn, wqkv_l, bqkv_l, nullptr, qkv, 1536, 512, 2);
        attn_kernel<<<BATCH * 8 * 8 * NHEAD, 128>>>(qkv, tbl_l, ao);
        gemm_mma<<<dim3(512 / 128, TOK / 256), 256, GEMM_SMEM>>>(
            ao, wo_l, bo_l, x, x, 512, 512, 0);
        ln_kernel<<<TOK, 128>>>(x, ln2_g + l * DD, ln2_b + l * DD, hb);
        gemm_mma<<<dim3(2048 / 128, TOK / 256), 256, GEMM_SMEM>>>(
            hb, w1_l, b1_l, nullptr, hid, 2048, 512, 1);
        gemm_mma<<<dim3(512 / 128, TOK / 256), 256, GEMM_SMEM>>>(
            hid, w2_l, b2_l, x, x, 512, 2048, 0);
    }
}

// round 16
// speedup vs baseline: 1.6981x; 1.6981x over previous
#include <cuda_runtime.h>
#include <cuda_fp16.h>
#include <math.h>
#include <stdint.h>

// Problem constants
#define BATCH 8
#define HH 64
#define WW 64
#define DD 512
#define NHEAD 16
#define DK 32
#define WS 8
#define SHIFT 4
#define TOK (BATCH*HH*WW)      // 32768
#define LAYERS 4
#define SCALE 0.17677669529663687f  // 1/sqrt(32)

// -------------------- scratch (allocation-free: __device__ globals) ------------
__device__ __align__(128) __half g_xn  [ (size_t)TOK * DD ];        // 32 MB
__device__ __align__(128) __half g_hb  [ (size_t)TOK * DD ];        // 32 MB
__device__ __align__(128) __half g_ao  [ (size_t)TOK * DD ];        // 32 MB
__device__ __align__(128) __half g_hid [ (size_t)TOK * 4 * DD ];    // 128 MB
__device__ __align__(128) __half g_wf  [ 12582912 ];                // 24 MB, fp16 [N][K]
__device__ __align__(128) __half g_qkvh[ (size_t)TOK * 3 * DD ];    // 96 MB fp16 q|k|v
__device__ float g_bqkv[ LAYERS * 3 * DD ];

// ==================== helpers ==================================================
__device__ __forceinline__ uint32_t smem_u32(const void* p) {
    uint32_t a;
    asm("{ .reg .u64 t; cvta.to.shared.u64 t, %1; cvt.u32.u64 %0, t; }" : "=r"(a) : "l"(p));
    return a;
}
#define CP_ASYNC16(dst, src) \
    asm volatile("cp.async.cg.shared.global [%0], [%1], 16;" :: "r"(dst), "l"(src))
#define CP_COMMIT() asm volatile("cp.async.commit_group;" ::: "memory")
#define CP_WAIT1()  asm volatile("cp.async.wait_group 1;" ::: "memory")
#define CP_WAIT0()  asm volatile("cp.async.wait_group 0;" ::: "memory")

__device__ __forceinline__ void ldmx4(uint32_t& r0, uint32_t& r1, uint32_t& r2, uint32_t& r3,
                                      uint32_t addr) {
    asm volatile("ldmatrix.sync.aligned.m8n8.x4.shared.b16 {%0,%1,%2,%3}, [%4];"
                 : "=r"(r0), "=r"(r1), "=r"(r2), "=r"(r3) : "r"(addr));
}
__device__ __forceinline__ void ldmx4t(uint32_t& r0, uint32_t& r1, uint32_t& r2, uint32_t& r3,
                                       uint32_t addr) {
    asm volatile("ldmatrix.sync.aligned.m8n8.x4.trans.shared.b16 {%0,%1,%2,%3}, [%4];"
                 : "=r"(r0), "=r"(r1), "=r"(r2), "=r"(r3) : "r"(addr));
}
__device__ __forceinline__ void mma16816(float* d, uint32_t a0, uint32_t a1, uint32_t a2,
                                         uint32_t a3, uint32_t b0, uint32_t b1) {
    asm volatile("mma.sync.aligned.m16n8k16.row.col.f32.f16.f16.f32 "
                 "{%0,%1,%2,%3},{%4,%5,%6,%7},{%8,%9},{%0,%1,%2,%3};"
                 : "+f"(d[0]), "+f"(d[1]), "+f"(d[2]), "+f"(d[3])
                 : "r"(a0), "r"(a1), "r"(a2), "r"(a3), "r"(b0), "r"(b1));
}

__device__ __forceinline__ float gelu_tanh(float x) {
    float x3 = x * x * x;
    return 0.5f * x * (1.0f + tanhf(0.7978845608028654f * (x + 0.044715f * x3)));
}
__device__ __forceinline__ uint32_t packh2(float a, float b) {
    __half2 h = __floats2half2_rn(a, b);
    return *(uint32_t*)&h;
}

// ==================== fused QKV weight convert + bias concat ===================
__global__ void convqkv_kernel(const float* __restrict__ Wq, const float* __restrict__ Wkv,
                               const float* __restrict__ bq, const float* __restrict__ bkv,
                               __half* __restrict__ dst, float* __restrict__ bias) {
    int l = blockIdx.z;
    if (blockIdx.y == 16) {
        if (blockIdx.x != 0) return;
        int t = threadIdx.y * 32 + threadIdx.x;
        for (int i = t; i < 1536; i += 256)
            bias[l * 1536 + i] = (i < 512) ? bq[l * 512 + i] : bkv[l * 1024 + (i - 512)];
        return;
    }
    __shared__ float tt[32][33];
    int n0 = blockIdx.x * 32, k0 = blockIdx.y * 32;
    const float* src;
    int N, nc0;
    if (n0 < 512) { src = Wq + (size_t)l * 512 * 512; N = 512; nc0 = n0; }
    else          { src = Wkv + (size_t)l * 512 * 1024; N = 1024; nc0 = n0 - 512; }
    dst += (size_t)l * 1536 * 512;
    int tx = threadIdx.x, ty = threadIdx.y;
#pragma unroll
    for (int i = 0; i < 4; i++)
        tt[ty + i * 8][tx] = src[(size_t)(k0 + ty + i * 8) * N + nc0 + tx];
    __syncthreads();
#pragma unroll
    for (int i = 0; i < 4; i++)
        dst[(size_t)(n0 + ty + i * 8) * 512 + k0 + tx] = __float2half_rn(tt[tx][ty + i * 8]);
}

// ==================== weight convert: W[K,N] -> Wf[N,K] fp16 ===================
__global__ void convw_kernel(const float* __restrict__ src, __half* __restrict__ dst,
                             int K, int N, size_t zstride) {
    __shared__ float t[32][33];
    int n0 = blockIdx.x * 32, k0 = blockIdx.y * 32;
    src += (size_t)blockIdx.z * K * N;
    dst += (size_t)blockIdx.z * zstride;
    int tx = threadIdx.x, ty = threadIdx.y;
#pragma unroll
    for (int i = 0; i < 4; i++)
        t[ty + i * 8][tx] = src[(size_t)(k0 + ty + i * 8) * N + n0 + tx];
    __syncthreads();
#pragma unroll
    for (int i = 0; i < 4; i++) {
        int n = n0 + ty + i * 8;
        int k = k0 + tx;
        dst[(size_t)n * K + k] = __float2half_rn(t[tx][ty + i * 8]);
    }
}

// ==================== LayerNorm -> fp16 ========================================
__global__ __launch_bounds__(128) void ln_kernel(const float* __restrict__ x,
                                                 const float* __restrict__ gamma,
                                                 const float* __restrict__ beta,
                                                 __half* __restrict__ out) {
    int tok = blockIdx.x;
    int tid = threadIdx.x;
    const float* xr = x + (size_t)tok * DD;
    float v[4];
#pragma unroll
    for (int i = 0; i < 4; i++) v[i] = xr[tid + i * 128];

    __shared__ float s1[4], s2[4];
    int lane = tid & 31, warp = tid >> 5;

    float s = v[0] + v[1] + v[2] + v[3];
#pragma unroll
    for (int o = 16; o > 0; o >>= 1) s += __shfl_xor_sync(0xffffffffu, s, o);
    if (lane == 0) s1[warp] = s;
    __syncthreads();
    float mean = (s1[0] + s1[1] + s1[2] + s1[3]) * (1.0f / DD);

    float sq = 0.f;
#pragma unroll
    for (int i = 0; i < 4; i++) { float d = v[i] - mean; sq += d * d; }
#pragma unroll
    for (int o = 16; o > 0; o >>= 1) sq += __shfl_xor_sync(0xffffffffu, sq, o);
    if (lane == 0) s2[warp] = sq;
    __syncthreads();
    float var = (s2[0] + s2[1] + s2[2] + s2[3]) * (1.0f / DD);
    float rs = rsqrtf(var + 1e-5f);

    __half* orow = out + (size_t)tok * DD;
#pragma unroll
    for (int i = 0; i < 4; i++) {
        int c = tid + i * 128;
        orow[c] = __float2half_rn((v[i] - mean) * rs * gamma[c] + beta[c]);
    }
}

// ==================== fp16 mma GEMM (128x128 tile, 2 CTAs/SM) ==================
// C[M,N] = epilogue(A[M,K] @ Wf[N,K]^T)
// mode 0: fp32 out (+bias, +optional resid)
// mode 1: gelu -> fp16 out      mode 2: bias only -> fp16 out
#define GBK 64
#define GSTAGES 3
#define GSTAGE_BYTES 32768
#define GSB_OFF 16384
#define GEMM_SMEM (GSTAGES * GSTAGE_BYTES)

__global__ __launch_bounds__(256, 2) void gemm_mma(const __half* __restrict__ A,
                                                   const __half* __restrict__ Wf,
                                                   const float* __restrict__ bias,
                                                   const float* __restrict__ resid,
                                                   void* __restrict__ Cout,
                                                   int N, int K, int mode) {
    extern __shared__ char smem[];
    uint32_t sb = smem_u32(smem);
    int tid = threadIdx.x, wid = tid >> 5, lane = tid & 31;
    int bm0 = blockIdx.y * 128, bn0 = blockIdx.x * 128;
    int wm = (wid & 3) * 32, wn = (wid >> 2) * 64;

    float acc[2][8][4];
#pragma unroll
    for (int t = 0; t < 2; t++)
#pragma unroll
        for (int n = 0; n < 8; n++)
#pragma unroll
            for (int r = 0; r < 4; r++) acc[t][n][r] = 0.f;

    const int nch = K >> 6;

    int lr = tid >> 1;
    int lc0 = (tid & 1) * 4;
    const __half* agp = A + (size_t)(bm0 + lr) * K + lc0 * 8;
    const __half* bgp = Wf + (size_t)(bn0 + lr) * K + lc0 * 8;
    uint32_t sw[4];
#pragma unroll
    for (int it = 0; it < 4; it++)
        sw[it] = (uint32_t)lr * 128 + (uint32_t)(((lc0 + it) ^ (lr & 7)) << 4);

    int arow[2], arx[2];
#pragma unroll
    for (int t = 0; t < 2; t++) {
        int r = wm + t * 16 + (lane & 15);
        arow[t] = r * 128;
        arx[t] = r & 7;
    }
    int ach = lane >> 4;
    int brow[4], brx[4];
#pragma unroll
    for (int p = 0; p < 4; p++) {
        int n = wn + p * 16 + (lane & 7) + ((lane >> 4) << 3);
        brow[p] = n * 128;
        brx[p] = n & 7;
    }
    int bch = (lane >> 3) & 1;

    auto issue_stage = [&](int c, int stage) {
        uint32_t st = sb + (uint32_t)stage * GSTAGE_BYTES;
        const __half* ag = agp + (size_t)c * GBK;
        const __half* bg = bgp + (size_t)c * GBK;
#pragma unroll
        for (int it = 0; it < 4; it++) CP_ASYNC16(st + sw[it], ag + it * 8);
#pragma unroll
        for (int it = 0; it < 4; it++) CP_ASYNC16(st + GSB_OFF + sw[it], bg + it * 8);
        CP_COMMIT();
    };

    issue_stage(0, 0);
    issue_stage(1, 1);

    int buf = 0, nbuf = 2;
    for (int c = 0; c < nch; c++) {
        if (c == nch - 1) { CP_WAIT0(); } else { CP_WAIT1(); }
        __syncthreads();
        // safe: the sync above guarantees all warps finished reading buffer
        // (c-1)%3 before anyone overwrites it below; no trailing sync needed.
        if (c + 2 < nch) issue_stage(c + 2, nbuf);

        uint32_t stA = sb + (uint32_t)buf * GSTAGE_BYTES;
        uint32_t stB = stA + GSB_OFF;
#pragma unroll
        for (int ks = 0; ks < 4; ks++) {
            uint32_t a0[4], a1[4];
            {
                uint32_t ad0 = stA + arow[0] + (uint32_t)((((ks << 1) + ach) ^ arx[0]) << 4);
                ldmx4(a0[0], a0[1], a0[2], a0[3], ad0);
                uint32_t ad1 = stA + arow[1] + (uint32_t)((((ks << 1) + ach) ^ arx[1]) << 4);
                ldmx4(a1[0], a1[1], a1[2], a1[3], ad1);
            }
#pragma unroll
            for (int p = 0; p < 4; p++) {
                uint32_t b0, b1, b2, b3;
                uint32_t bd = stB + brow[p] + (uint32_t)((((ks << 1) + bch) ^ brx[p]) << 4);
                ldmx4(b0, b1, b2, b3, bd);
                mma16816(acc[0][2 * p],     a0[0], a0[1], a0[2], a0[3], b0, b1);
                mma16816(acc[0][2 * p + 1], a0[0], a0[1], a0[2], a0[3], b2, b3);
                mma16816(acc[1][2 * p],     a1[0], a1[1], a1[2], a1[3], b0, b1);
                mma16816(acc[1][2 * p + 1], a1[0], a1[1], a1[2], a1[3], b2, b3);
            }
        }
        buf = (buf + 1 == GSTAGES) ? 0 : buf + 1;
        nbuf = (nbuf + 1 == GSTAGES) ? 0 : nbuf + 1;
    }

    int cbase = bn0 + wn;
#pragma unroll
    for (int t = 0; t < 2; t++) {
        int r0 = bm0 + wm + t * 16 + (lane >> 2);
#pragma unroll
        for (int half = 0; half < 2; half++) {
            int r = r0 + half * 8;
            if (mode == 0) {
                float* crow = (float*)Cout + (size_t)r * N + cbase;
                const float* rrow = resid ? resid + (size_t)r * N + cbase : (const float*)0;
#pragma unroll
                for (int p = 0; p < 8; p++) {
                    int c = p * 8 + (lane & 3) * 2;
                    float v0 = acc[t][p][half * 2 + 0] + bias[cbase + c];
                    float v1 = acc[t][p][half * 2 + 1] + bias[cbase + c + 1];
                    if (rrow) { v0 += rrow[c]; v1 += rrow[c + 1]; }
                    float2 o; o.x = v0; o.y = v1;
                    *(float2*)(crow + c) = o;
                }
            } else {
                __half* orow = (__half*)Cout + (size_t)r * N;
                int do_g = (mode == 1);
#pragma unroll
                for (int p = 0; p < 8; p++) {
                    int c = p * 8 + (lane & 3) * 2;
                    float v0 = acc[t][p][half * 2 + 0] + bias[cbase + c];
                    float v1 = acc[t][p][half * 2 + 1] + bias[cbase + c + 1];
                    if (do_g) { v0 = gelu_tanh(v0); v1 = gelu_tanh(v1); }
                    int cn = cbase + c;
                    *(uint32_t*)(orow + cn) = packh2(v0, v1);
                }
            }
        }
    }
}

// ==================== Tensor-core shifted-window attention =====================
__device__ __forceinline__ int region_id(int hs, int ws) {
    int rh = (hs < HH - WS) ? 0 : (hs < HH - SHIFT) ? 1 : 2;
    int rw = (ws < WW - WS) ? 0 : (ws < WW - SHIFT) ? 1 : 2;
    return rh * 3 + rw;
}

// one block per (batch, window, head); 4 warps x 16 queries
__global__ __launch_bounds__(128) void attn_kernel(const __half* __restrict__ qkv,
                                                   const float* __restrict__ table,
                                                   __half* __restrict__ out) {
    __shared__ __align__(16) __half Qs[64][40];
    __shared__ __align__(16) __half Ks[64][40];
    __shared__ __align__(16) __half Vs[64][40];
    __shared__ float T[225];
    __shared__ char RG[64];

    int bi = blockIdx.x;
    int nh  = bi & 15; bi >>= 4;
    int nww = bi & 7;  bi >>= 3;
    int nwh = bi & 7;  bi >>= 3;
    int b = bi;
    int tid = threadIdx.x;
    int lane = tid & 31, wid = tid >> 5;

    for (int i = tid; i < 225; i += 128) T[i] = table[i * NHEAD + nh];
    if (tid < 64)
        RG[tid] = (char)region_id(nwh * WS + (tid >> 3), nww * WS + (tid & 7));

    for (int idx = tid; idx < 256; idx += 128) {
        int e = idx >> 2, c = idx & 3;
        int h = (nwh * WS + (e >> 3) + SHIFT) & (HH - 1);
        int w = (nww * WS + (e & 7) + SHIFT) & (WW - 1);
        size_t tok = ((size_t)b * HH + h) * WW + w;
        const __half* base = qkv + tok * (3 * DD) + nh * DK + c * 8;
        *(uint4*)&Qs[e][c * 8] = *(const uint4*)(base);
        *(uint4*)&Ks[e][c * 8] = *(const uint4*)(base + DD);
        *(uint4*)&Vs[e][c * 8] = *(const uint4*)(base + 2 * DD);
    }
    __syncthreads();

    int qbase = wid * 16;
    int lrow = (lane & 7) + ((lane >> 3) & 1) * 8;
    int lcol = (lane >> 4) * 8;

    uint32_t aq[2][4];
#pragma unroll
    for (int k2 = 0; k2 < 2; k2++) {
        uint32_t ad = smem_u32(&Qs[qbase + lrow][k2 * 16 + lcol]);
        ldmx4(aq[k2][0], aq[k2][1], aq[k2][2], aq[k2][3], ad);
    }

    float sacc[8][4];
#pragma unroll
    for (int j = 0; j < 8; j++) {
        sacc[j][0] = sacc[j][1] = sacc[j][2] = sacc[j][3] = 0.f;
        uint32_t bk[4];
        uint32_t bd = smem_u32(&Ks[8 * j + (lane & 7)][(lane >> 3) * 8]);
        ldmx4(bk[0], bk[1], bk[2], bk[3], bd);
        mma16816(sacc[j], aq[0][0], aq[0][1], aq[0][2], aq[0][3], bk[0], bk[1]);
        mma16816(sacc[j], aq[1][0], aq[1][1], aq[1][2], aq[1][3], bk[2], bk[3]);
    }

    int g = lane >> 2, qp = lane & 3;
    int q0 = qbase + g, q1 = q0 + 8;
    int iq0 = q0 >> 3, jq = q0 & 7;
    int iq1 = q1 >> 3;
    char rg0 = RG[q0], rg1 = RG[q1];
    float m0 = -1e30f, m1 = -1e30f;
#pragma unroll
    for (int j = 0; j < 8; j++) {
#pragma unroll
        for (int c = 0; c < 4; c++) {
            int e = 8 * j + 2 * qp + (c & 1);
            int ik = e >> 3, jk = e & 7;
            int iqr = (c < 2) ? iq0 : iq1;
            char rgr = (c < 2) ? rg0 : rg1;
            float s = sacc[j][c] * SCALE + T[(iqr - ik + 7) * 15 + (jq - jk + 7)];
            if (RG[e] != rgr) s = -1e9f;
            sacc[j][c] = s;
            if (c < 2) m0 = fmaxf(m0, s); else m1 = fmaxf(m1, s);
        }
    }
    m0 = fmaxf(m0, __shfl_xor_sync(0xffffffffu, m0, 1));
    m0 = fmaxf(m0, __shfl_xor_sync(0xffffffffu, m0, 2));
    m1 = fmaxf(m1, __shfl_xor_sync(0xffffffffu, m1, 1));
    m1 = fmaxf(m1, __shfl_xor_sync(0xffffffffu, m1, 2));

    float d0 = 0.f, d1 = 0.f;
#pragma unroll
    for (int j = 0; j < 8; j++) {
#pragma unroll
        for (int c = 0; c < 4; c++) {
            float p = expf(sacc[j][c] - ((c < 2) ? m0 : m1));
            sacc[j][c] = p;
            if (c < 2) d0 += p; else d1 += p;
        }
    }
    d0 += __shfl_xor_sync(0xffffffffu, d0, 1);
    d0 += __shfl_xor_sync(0xffffffffu, d0, 2);
    d1 += __shfl_xor_sync(0xffffffffu, d1, 1);
    d1 += __shfl_xor_sync(0xffffffffu, d1, 2);
    float inv0 = 1.0f / d0, inv1 = 1.0f / d1;

    uint32_t ap[4][4];
#pragma unroll
    for (int t = 0; t < 4; t++) {
        ap[t][0] = packh2(sacc[2 * t][0],     sacc[2 * t][1]);
        ap[t][1] = packh2(sacc[2 * t][2],     sacc[2 * t][3]);
        ap[t][2] = packh2(sacc[2 * t + 1][0], sacc[2 * t + 1][1]);
        ap[t][3] = packh2(sacc[2 * t + 1][2], sacc[2 * t + 1][3]);
    }

    float oacc[4][4];
#pragma unroll
    for (int m = 0; m < 4; m++)
        oacc[m][0] = oacc[m][1] = oacc[m][2] = oacc[m][3] = 0.f;
#pragma unroll
    for (int u = 0; u < 4; u++) {
        uint32_t bv[8];
        uint32_t vd0 = smem_u32(&Vs[16 * u + lrow][lcol]);
        ldmx4t(bv[0], bv[1], bv[2], bv[3], vd0);
        uint32_t vd1 = smem_u32(&Vs[16 * u + lrow][16 + lcol]);
        ldmx4t(bv[4], bv[5], bv[6], bv[7], vd1);
#pragma unroll
        for (int m = 0; m < 4; m++)
            mma16816(oacc[m], ap[u][0], ap[u][1], ap[u][2], ap[u][3],
                     bv[2 * m], bv[2 * m + 1]);
    }

    int h0 = (nwh * WS + iq0 + SHIFT) & (HH - 1);
    int h1 = (nwh * WS + iq1 + SHIFT) & (HH - 1);
    int w0 = (nww * WS + jq + SHIFT) & (WW - 1);
    size_t t0 = ((size_t)b * HH + h0) * WW + w0;
    size_t t1 = ((size_t)b * HH + h1) * WW + w0;
    __half* o0 = out + t0 * DD + nh * DK + 2 * qp;
    __half* o1 = out + t1 * DD + nh * DK + 2 * qp;
#pragma unroll
    for (int m = 0; m < 4; m++) {
        *(uint32_t*)(o0 + 8 * m) = packh2(oacc[m][0] * inv0, oacc[m][1] * inv0);
        *(uint32_t*)(o1 + 8 * m) = packh2(oacc[m][2] * inv1, oacc[m][3] * inv1);
    }
}

// ==================== driver ===================================================
extern "C" void kernel_launch(void* const* d_in, const int* in_sizes, int n_in,
                              void* d_out, int out_size) {
    const float* x_in      = (const float*)d_in[0];
    const float* Wq        = (const float*)d_in[3];
    const float* bq        = (const float*)d_in[4];
    const float* Wkv       = (const float*)d_in[5];
    const float* bkv       = (const float*)d_in[6];
    const float* Wo        = (const float*)d_in[7];
    const float* bo        = (const float*)d_in[8];
    const float* rel_table = (const float*)d_in[9];
    const float* ln1_g     = (const float*)d_in[10];
    const float* ln1_b     = (const float*)d_in[11];
    const float* ln2_g     = (const float*)d_in[12];
    const float* ln2_b     = (const float*)d_in[13];
    const float* W1        = (const float*)d_in[14];
    const float* b1        = (const float*)d_in[15];
    const float* W2        = (const float*)d_in[16];
    const float* b2        = (const float*)d_in[17];

    float* x = (float*)d_out;

    __half *xn, *hb, *ao, *hid, *wf, *qkv;
    float *bqkv;
    cudaGetSymbolAddress((void**)&xn,   g_xn);
    cudaGetSymbolAddress((void**)&hb,   g_hb);
    cudaGetSymbolAddress((void**)&ao,   g_ao);
    cudaGetSymbolAddress((void**)&hid,  g_hid);
    cudaGetSymbolAddress((void**)&wf,   g_wf);
    cudaGetSymbolAddress((void**)&qkv,  g_qkvh);
    cudaGetSymbolAddress((void**)&bqkv, g_bqkv);

    cudaFuncSetAttribute(gemm_mma, cudaFuncAttributeMaxDynamicSharedMemorySize, GEMM_SMEM);

    const size_t off_qkv = 0;                                   // [1536][512] per layer
    const size_t off_o   = off_qkv + (size_t)LAYERS * 1536 * 512;
    const size_t off_1   = off_o   + (size_t)LAYERS * 512 * 512;
    const size_t off_2   = off_1   + (size_t)LAYERS * 2048 * 512;

    dim3 tb(32, 8);
    convqkv_kernel<<<dim3(48, 17, LAYERS), tb>>>(Wq, Wkv, bq, bkv, wf + off_qkv, bqkv);
    convw_kernel<<<dim3(512 / 32,  512 / 32,  LAYERS), tb>>>(Wo, wf + off_o, 512, 512,
                                                             (size_t)512 * 512);
    convw_kernel<<<dim3(2048 / 32, 512 / 32,  LAYERS), tb>>>(W1, wf + off_1, 512, 2048,
                                                             (size_t)2048 * 512);
    convw_kernel<<<dim3(512 / 32,  2048 / 32, LAYERS), tb>>>(W2, wf + off_2, 2048, 512,
                                                             (size_t)512 * 2048);

    cudaMemcpyAsync(x, x_in, (size_t)TOK * DD * sizeof(float),
                    cudaMemcpyDeviceToDevice, 0);

    for (int l = 0; l < LAYERS; l++) {
        const __half* wqkv_l = wf + off_qkv + (size_t)l * 1536 * 512;
        const __half* wo_l   = wf + off_o   + (size_t)l * 512 * 512;
        const __half* w1_l   = wf + off_1   + (size_t)l * 2048 * 512;
        const __half* w2_l   = wf + off_2   + (size_t)l * 512 * 2048;
        const float* bqkv_l = bqkv + (size_t)l * 3 * DD;
        const float* bo_l   = bo   + (size_t)l * DD;
        const float* tbl_l  = rel_table + (size_t)l * 225 * NHEAD;
        const float* b1_l   = b1   + (size_t)l * 4 * DD;
        const float* b2_l   = b2   + (size_t)l * DD;

        ln_kernel<<<TOK, 128>>>(x, ln1_g + l * DD, ln1_b + l * DD, xn);
        gemm_mma<<<dim3(1536 / 128, TOK / 128), 256, GEMM_SMEM>>>(
            xn, wqkv_l, bqkv_l, nullptr, qkv, 1536, 512, 2);
        attn_kernel<<<BATCH * 8 * 8 * NHEAD, 128>>>(qkv, tbl_l, ao);
        gemm_mma<<<dim3(512 / 128, TOK / 128), 256, GEMM_SMEM>>>(
            ao, wo_l, bo_l, x, x, 512, 512, 0);
        ln_kernel<<<TOK, 128>>>(x, ln2_g + l * DD, ln2_b + l * DD, hb);
        gemm_mma<<<dim3(2048 / 128, TOK / 128), 256, GEMM_SMEM>>>(
            hb, w1_l, b1_l, nullptr, hid, 2048, 512, 1);
        gemm_mma<<<dim3(512 / 128, TOK / 128), 256, GEMM_SMEM>>>(
            hid, w2_l, b2_l, x, x, 512, 2048, 0);
    }
}